// round 15
// baseline (speedup 1.0000x reference)
#include <cuda_runtime.h>
#include <math_constants.h>

#define B       4
#define M       76800          // 240*320 targets per batch
#define NC      256
#define NBLK    300            // 75 chunks x 4 batches; b = bid&3, sub = bid>>2; 1024 targets/block

__device__ unsigned g_maxkey;          // monotonic masked-max key (idempotent across replays)
__device__ int      g_anyinv;          // any masked-out pixel (idempotent)
__device__ float    g_csort[B * NC];   // sorted centers (published by bids 0..3)
__device__ int      g_start[B * NC];   // bucket-start LUT (published by bids 0..3)
__device__ float    g_meta[B * 2];     // {lo, scale} per batch
__device__ unsigned g_flag[B];         // release flag (reset by final combiner)
__device__ unsigned g_ckey[B * NC];    // min dist per sorted slot, INVERTED key; 0 == +inf (reset by DT blocks)
__device__ float    g_d2part[NBLK];
__device__ float    g_dmin[B * NC];    // per-slot DT result (pre-pad clamp)
__device__ float    g_bsum[B];         // per-batch d2part sums
__device__ unsigned g_done[B];         // per-batch tickets (reset by final combiner)
__device__ unsigned g_cnt2;            // DT-completion ticket (reset by final combiner)

__device__ __forceinline__ unsigned fkey(float f) {
    unsigned b = __float_as_uint(f);
    return b ^ ((b & 0x80000000u) ? 0xFFFFFFFFu : 0x80000000u);
}
__device__ __forceinline__ float funkey(unsigned k) {
    return __uint_as_float(k ^ ((k & 0x80000000u) ? 0x80000000u : 0xFFFFFFFFu));
}

// inclusive prefix-min over 256 threads (2 barriers)
__device__ __forceinline__ float blk_min_scan(float v, int tid, float* wa8) {
    #pragma unroll
    for (int o = 1; o < 32; o <<= 1) {
        float u = __shfl_up_sync(0xFFFFFFFFu, v, o);
        if ((tid & 31) >= o) v = fminf(v, u);
    }
    if ((tid & 31) == 31) wa8[tid >> 5] = v;
    __syncthreads();
    float pre = CUDART_INF_F;
    const int w = tid >> 5;
    #pragma unroll
    for (int j = 0; j < 7; j++)
        if (j < w) pre = fminf(pre, wa8[j]);
    __syncthreads();
    return fminf(v, pre);
}
// inclusive suffix-min over 256 threads (2 barriers)
__device__ __forceinline__ float blk_min_scan_rev(float v, int tid, float* wa8) {
    #pragma unroll
    for (int o = 1; o < 32; o <<= 1) {
        float u = __shfl_down_sync(0xFFFFFFFFu, v, o);
        if ((tid & 31) + o < 32) v = fminf(v, u);
    }
    if ((tid & 31) == 0) wa8[tid >> 5] = v;
    __syncthreads();
    float pre = CUDART_INF_F;
    const int w = tid >> 5;
    #pragma unroll
    for (int j = 1; j < 8; j++)
        if (j > w) pre = fminf(pre, wa8[j]);
    __syncthreads();
    return fminf(v, pre);
}

__global__ void __launch_bounds__(256) k_fused(const float4* __restrict__ t4,
                                               const int4*   __restrict__ m4,
                                               const float*  __restrict__ centers,
                                               float*        __restrict__ out) {
    __shared__ float    scs[NC];
    __shared__ float    cval[NC];
    __shared__ int      cidx[NC];
    __shared__ int      hist[NC];
    __shared__ int      start[NC + 1];
    __shared__ unsigned scmin[NC];
    __shared__ float    wa[16];
    __shared__ int      swa[8];
    __shared__ float    sred[8], sred2[8];
    __shared__ float    smeta[2];
    __shared__ int      sfast;
    __shared__ bool     sdone, sfin;

    const int tid  = threadIdx.x;      // 0..255
    const int bid  = blockIdx.x;
    const int lane = tid & 31;
    const int wid  = tid >> 5;         // 0..7
    const int b    = bid & 3;
    const int sub  = bid >> 2;         // 0..74

    // ---- kick off DRAM loads first (float4/int4: 4 targets/thread) ----
    const int gi = b * (M / 4) + sub * 256 + tid;
    const float4 tv = t4[gi];
    const int4   mv = m4[gi];
    const float tval[4] = {tv.x, tv.y, tv.z, tv.w};
    const int   mok[4]  = {mv.x, mv.y, mv.z, mv.w};

    scmin[tid] = 0x7F800000u;          // +inf

    // ---- opportunistic fast path: use published sorted data if ready ----
    if (tid == 0) sfast = (bid >= B) && (__ldcg(&g_flag[b]) != 0u);
    __syncthreads();

    float lo, scale;
    if (sfast) {
        __threadfence();               // acquire after flag observe
        scs[tid]   = __ldcg(&g_csort[b * NC + tid]);
        start[tid] = __ldcg(&g_start[b * NC + tid]);
        if (tid == 0) {
            start[NC] = NC;
            smeta[0] = __ldcg(&g_meta[2 * b]);
            smeta[1] = __ldcg(&g_meta[2 * b + 1]);
        }
        __syncthreads();
        lo = smeta[0]; scale = smeta[1];
    } else {
        // local deterministic counting sort
        const float myc = centers[b * NC + tid];
        hist[tid] = 0;
        __syncthreads();
        {
            float mn = myc, mx = myc;
            #pragma unroll
            for (int o = 16; o; o >>= 1) {
                mn = fminf(mn, __shfl_xor_sync(0xFFFFFFFFu, mn, o));
                mx = fmaxf(mx, __shfl_xor_sync(0xFFFFFFFFu, mx, o));
            }
            if (lane == 0) { wa[wid] = mn; wa[8 + wid] = mx; }
        }
        __syncthreads();
        lo = wa[0]; float hi = wa[8];
        #pragma unroll
        for (int j = 1; j < 8; j++) { lo = fminf(lo, wa[j]); hi = fmaxf(hi, wa[8 + j]); }
        scale = (hi > lo) ? 256.0f / (hi - lo) : 0.0f;

        const int myq = min(255, max(0, (int)((myc - lo) * scale)));
        const int myrank = atomicAdd(&hist[myq], 1);
        __syncthreads();
        {
            int h = hist[tid], incl = h;
            #pragma unroll
            for (int o = 1; o < 32; o <<= 1) {
                int u = __shfl_up_sync(0xFFFFFFFFu, incl, o);
                if (lane >= o) incl += u;
            }
            if (lane == 31) swa[wid] = incl;
            __syncthreads();
            int add = 0;
            #pragma unroll
            for (int j = 0; j < 8; j++)
                if (j < wid) add += swa[j];
            start[tid] = add + incl - h;
            if (tid == 0) start[NC] = NC;
        }
        __syncthreads();
        {
            int p = start[myq] + myrank;
            cval[p] = myc; cidx[p] = tid;
        }
        __syncthreads();
        {
            const int s0 = start[myq], e0 = start[myq + 1];
            int rb = 0;
            for (int j = s0; j < e0; j++) {
                float cv = cval[j];
                if (cv < myc || (cv == myc && cidx[j] < tid)) rb++;
            }
            scs[s0 + rb] = myc;
        }
        __syncthreads();

        if (bid < B) {                 // publish
            g_csort[b * NC + tid] = scs[tid];
            g_start[b * NC + tid] = start[tid];
            if (tid == 0) { g_meta[2 * b] = lo; g_meta[2 * b + 1] = scale; }
            __threadfence();
            __syncthreads();
            if (tid == 0) atomicExch(&g_flag[b], 1u);
        }
    }

    // ---- main pass: 4 targets, bucket-LUT bracket (independent chains -> ILP) ----
    float s = 0.0f;
    float mloc = -CUDART_INF_F;
    int inv = 0;
    #pragma unroll
    for (int q = 0; q < 4; q++) {
        const float tk = tval[q];
        if (mok[q]) {
            mloc = fmaxf(mloc, tk);
            int qt = min(255, max(0, (int)((tk - lo) * scale)));
            int j = start[qt], e = start[qt + 1];
            while (j < e && scs[j] <= tk) j++;     // exact lower-bound count
            float dlo = (j >= 1) ? tk - scs[j - 1] : CUDART_INF_F;
            float dhi = (j < NC) ? scs[j] - tk     : CUDART_INF_F;
            float d = fminf(dlo, dhi);
            s += d * d;
            if (j >= 1) atomicMin(&scmin[j - 1], __float_as_uint(dlo));
            if (j < NC) atomicMin(&scmin[j],     __float_as_uint(dhi));
        } else {
            inv = 1;
        }
    }

    #pragma unroll
    for (int o = 16; o; o >>= 1) {
        s    += __shfl_xor_sync(0xFFFFFFFFu, s, o);
        mloc  = fmaxf(mloc, __shfl_xor_sync(0xFFFFFFFFu, mloc, o));
    }
    if (lane == 0) { sred[wid] = s; sred2[wid] = mloc; }
    int banyinv = __syncthreads_or(inv);

    {   // merge per-block center mins (inverted key; 0 == +inf)
        unsigned sm = scmin[tid];
        if (sm != 0x7F800000u) atomicMax(&g_ckey[b * NC + tid], ~sm);
    }
    if (tid == 0) {
        float bs = sred[0], bm = sred2[0];
        #pragma unroll
        for (int j = 1; j < 8; j++) { bs += sred[j]; bm = fmaxf(bm, sred2[j]); }
        g_d2part[bid] = bs;
        atomicMax(&g_maxkey, fkey(bm));
        if (banyinv) g_anyinv = 1;     // benign same-value race
    }

    // -------------------- per-batch ticket (75 arrivals) --------------------
    __threadfence();
    if (tid == 0) sdone = (atomicAdd(&g_done[b], 1u) == 75u - 1u);
    __syncthreads();
    if (!sdone) return;
    __threadfence();

    // ============ BATCH DT BLOCK: distance transform for batch b ============
    {
        float    c   = __ldcg(&g_csort[b * NC + tid]);
        unsigned key = __ldcg(&g_ckey[b * NC + tid]);
        g_ckey[b * NC + tid] = 0u;             // reset for next replay
        float d = key ? __uint_as_float(~key) : CUDART_INF_F;
        float As = blk_min_scan(d - c, tid, wa);
        float Bs = blk_min_scan_rev(d + c, tid, wa);
        g_dmin[b * NC + tid] = fminf(As + c, Bs - c);   // pre-pad-clamp DT

        // fixed-order sum of this batch's 75 d2part slots (bid = b + 4*t)
        float sacc = (tid < 75) ? g_d2part[b + 4 * tid] : 0.0f;
        #pragma unroll
        for (int o = 16; o; o >>= 1) sacc += __shfl_xor_sync(0xFFFFFFFFu, sacc, o);
        if (lane == 0) sred[wid] = sacc;
        __syncthreads();
        if (tid == 0) {
            float bs = sred[0] + sred[1] + sred[2];   // warps 0..2 cover tid<96
            g_bsum[b] = bs;
        }
    }

    // -------------------- global ticket (4 DT completions) --------------------
    __threadfence();
    if (tid == 0) sfin = (atomicAdd(&g_cnt2, 1u) == B - 1u);
    __syncthreads();
    if (!sfin) return;
    __threadfence();

    // ====================== FINAL COMBINE (cheap) ======================
    const float mt = funkey(g_maxkey);
    const float mc = fmaxf(fmaxf(__ldcg(&g_csort[NC - 1]),          __ldcg(&g_csort[NC + NC - 1])),
                           fmaxf(__ldcg(&g_csort[2 * NC + NC - 1]), __ldcg(&g_csort[3 * NC + NC - 1])));
    const float mx = fmaxf(mt, mc), mn = fminf(mt, mc);
    const float pad = mx + (mx - mn) + 1.0f;   // EPS = 1.0
    const int anyinv = g_anyinv;

    float acc = 0.0f;
    #pragma unroll
    for (int bb = 0; bb < B; bb++) {
        float Di = __ldcg(&g_dmin[bb * NC + tid]);
        float c  = __ldcg(&g_csort[bb * NC + tid]);
        if (anyinv) Di = fminf(Di, pad - c);
        acc += Di * Di;
    }
    if (tid == 0) {
        acc += g_bsum[0] + g_bsum[1] + g_bsum[2] + g_bsum[3];  // fixed order
        if (!anyinv) { float dp = pad - mt; acc += dp * dp; }  // pad-center row
        g_cnt2 = 0u;
        g_done[0] = 0u; g_done[1] = 0u; g_done[2] = 0u; g_done[3] = 0u;
        g_flag[0] = 0u; g_flag[1] = 0u; g_flag[2] = 0u; g_flag[3] = 0u;
    }

    #pragma unroll
    for (int o = 16; o; o >>= 1) acc += __shfl_xor_sync(0xFFFFFFFFu, acc, o);
    if (lane == 0) sred2[wid] = acc;
    __syncthreads();
    if (tid == 0) {
        float tot = sred2[0];
        #pragma unroll
        for (int j = 1; j < 8; j++) tot += sred2[j];
        out[0] = tot * 0.25f;
    }
}

// ---------------------------------------------------------------------------
extern "C" void kernel_launch(void* const* d_in, const int* in_sizes, int n_in,
                              void* d_out, int out_size) {
    const float4* t4      = (const float4*)d_in[0];
    const float*  centers = (const float*)d_in[1];
    const int4*   m4      = (const int4*)d_in[2];
    float*        out     = (float*)d_out;

    k_fused<<<NBLK, 256>>>(t4, m4, centers, out);
}

// round 16
// speedup vs baseline: 1.0361x; 1.0361x over previous
#include <cuda_runtime.h>
#include <math_constants.h>

#define B       4
#define M       76800          // 240*320 targets per batch
#define NC      256
#define NBLK    300            // 75 chunks x 4 batches; b = bid&3, sub = bid>>2; 1024 targets/block

__device__ unsigned g_maxkey;          // monotonic masked-max key (idempotent across replays)
__device__ int      g_anyinv;          // any masked-out pixel (idempotent)
__device__ float    g_csort[B * NC];   // sorted centers (published by bids 0..3)
__device__ int      g_start[B * NC];   // bucket-start LUT (published by bids 0..3)
__device__ float    g_meta[B * 2];     // {lo, scale} per batch
__device__ unsigned g_flag[B];         // release flag (reset by finalizer)
__device__ unsigned g_ckey[B * NC];    // min dist per sorted slot, INVERTED key; 0 == +inf (reset by finalizer)
__device__ float    g_d2part[NBLK];
__device__ unsigned g_cnt;             // ticket (reset by finalizer)

__device__ __forceinline__ unsigned fkey(float f) {
    unsigned b = __float_as_uint(f);
    return b ^ ((b & 0x80000000u) ? 0xFFFFFFFFu : 0x80000000u);
}
__device__ __forceinline__ float funkey(unsigned k) {
    return __uint_as_float(k ^ ((k & 0x80000000u) ? 0x80000000u : 0xFFFFFFFFu));
}

// inclusive prefix-min over 256 threads (2 barriers)
__device__ __forceinline__ float blk_min_scan(float v, int tid, float* wa8) {
    #pragma unroll
    for (int o = 1; o < 32; o <<= 1) {
        float u = __shfl_up_sync(0xFFFFFFFFu, v, o);
        if ((tid & 31) >= o) v = fminf(v, u);
    }
    if ((tid & 31) == 31) wa8[tid >> 5] = v;
    __syncthreads();
    float pre = CUDART_INF_F;
    const int w = tid >> 5;
    #pragma unroll
    for (int j = 0; j < 7; j++)
        if (j < w) pre = fminf(pre, wa8[j]);
    __syncthreads();
    return fminf(v, pre);
}
// inclusive suffix-min over 256 threads (2 barriers)
__device__ __forceinline__ float blk_min_scan_rev(float v, int tid, float* wa8) {
    #pragma unroll
    for (int o = 1; o < 32; o <<= 1) {
        float u = __shfl_down_sync(0xFFFFFFFFu, v, o);
        if ((tid & 31) + o < 32) v = fminf(v, u);
    }
    if ((tid & 31) == 0) wa8[tid >> 5] = v;
    __syncthreads();
    float pre = CUDART_INF_F;
    const int w = tid >> 5;
    #pragma unroll
    for (int j = 1; j < 8; j++)
        if (j > w) pre = fminf(pre, wa8[j]);
    __syncthreads();
    return fminf(v, pre);
}

__global__ void __launch_bounds__(256) k_fused(const float4* __restrict__ t4,
                                               const int4*   __restrict__ m4,
                                               const float*  __restrict__ centers,
                                               float*        __restrict__ out) {
    __shared__ float    scs[NC];       // sorted centers (identical content on both paths)
    __shared__ float    cval[NC];      // scatter scratch (slow path only)
    __shared__ int      cidx[NC];
    __shared__ int      hist[NC];
    __shared__ int      start[NC + 1];
    __shared__ unsigned scmin[NC];
    __shared__ float    wa[16];
    __shared__ int      swa[8];
    __shared__ float    sred[8], sred2[8];
    __shared__ float    smeta[2];
    __shared__ int      sfast;
    __shared__ bool     is_last;

    const int tid  = threadIdx.x;      // 0..255
    const int bid  = blockIdx.x;
    const int lane = tid & 31;
    const int wid  = tid >> 5;         // 0..7
    const int b    = bid & 3;
    const int sub  = bid >> 2;         // 0..74

    // ---- issue the (independent) flag probe FIRST so its L2 latency hides
    //      under the target DRAM loads below ----
    unsigned flagv = 0u;
    if (tid == 0 && bid >= B) flagv = __ldcg(&g_flag[b]);

    // ---- kick off DRAM loads (float4/int4: 4 targets/thread) ----
    const int gi = b * (M / 4) + sub * 256 + tid;
    const float4 tv = t4[gi];
    const int4   mv = m4[gi];
    const float tval[4] = {tv.x, tv.y, tv.z, tv.w};
    const int   mok[4]  = {mv.x, mv.y, mv.z, mv.w};

    scmin[tid] = 0x7F800000u;          // +inf
    if (tid == 0) sfast = (flagv != 0u);
    __syncthreads();

    float lo, scale;
    if (sfast) {
        // fast path: 2 coalesced L2 loads, content bitwise-identical to local sort
        __threadfence();               // acquire ordering after flag observe
        scs[tid]   = __ldcg(&g_csort[b * NC + tid]);
        start[tid] = __ldcg(&g_start[b * NC + tid]);
        if (tid == 0) {
            start[NC] = NC;
            smeta[0] = __ldcg(&g_meta[2 * b]);
            smeta[1] = __ldcg(&g_meta[2 * b + 1]);
        }
        __syncthreads();
        lo = smeta[0]; scale = smeta[1];
    } else {
        // slow path: local deterministic counting sort
        const float myc = centers[b * NC + tid];
        hist[tid] = 0;
        __syncthreads();
        {
            float mn = myc, mx = myc;
            #pragma unroll
            for (int o = 16; o; o >>= 1) {
                mn = fminf(mn, __shfl_xor_sync(0xFFFFFFFFu, mn, o));
                mx = fmaxf(mx, __shfl_xor_sync(0xFFFFFFFFu, mx, o));
            }
            if (lane == 0) { wa[wid] = mn; wa[8 + wid] = mx; }
        }
        __syncthreads();
        lo = wa[0]; float hi = wa[8];
        #pragma unroll
        for (int j = 1; j < 8; j++) { lo = fminf(lo, wa[j]); hi = fmaxf(hi, wa[8 + j]); }
        scale = (hi > lo) ? 256.0f / (hi - lo) : 0.0f;

        const int myq = min(255, max(0, (int)((myc - lo) * scale)));
        const int myrank = atomicAdd(&hist[myq], 1);
        __syncthreads();
        {
            int h = hist[tid], incl = h;
            #pragma unroll
            for (int o = 1; o < 32; o <<= 1) {
                int u = __shfl_up_sync(0xFFFFFFFFu, incl, o);
                if (lane >= o) incl += u;
            }
            if (lane == 31) swa[wid] = incl;
            __syncthreads();
            int add = 0;
            #pragma unroll
            for (int j = 0; j < 8; j++)
                if (j < wid) add += swa[j];
            start[tid] = add + incl - h;
            if (tid == 0) start[NC] = NC;
        }
        __syncthreads();
        {
            int p = start[myq] + myrank;
            cval[p] = myc; cidx[p] = tid;
        }
        __syncthreads();
        {
            const int s0 = start[myq], e0 = start[myq + 1];
            int rb = 0;
            for (int j = s0; j < e0; j++) {
                float cv = cval[j];
                if (cv < myc || (cv == myc && cidx[j] < tid)) rb++;
            }
            scs[s0 + rb] = myc;        // fully sorted, deterministic order
        }
        __syncthreads();

        if (bid < B) {                 // publish for fast-path blocks + finalizer
            g_csort[b * NC + tid] = scs[tid];
            g_start[b * NC + tid] = start[tid];
            if (tid == 0) { g_meta[2 * b] = lo; g_meta[2 * b + 1] = scale; }
            __threadfence();
            __syncthreads();
            if (tid == 0) atomicExch(&g_flag[b], 1u);
        }
    }

    // ---- main pass: 4 targets, bucket-LUT bracket (independent chains -> ILP) ----
    float s = 0.0f;
    float mloc = -CUDART_INF_F;
    int inv = 0;
    #pragma unroll
    for (int q = 0; q < 4; q++) {
        const float tk = tval[q];
        if (mok[q]) {
            mloc = fmaxf(mloc, tk);
            int qt = min(255, max(0, (int)((tk - lo) * scale)));
            int j = start[qt], e = start[qt + 1];
            while (j < e && scs[j] <= tk) j++;     // exact lower-bound count
            float dlo = (j >= 1) ? tk - scs[j - 1] : CUDART_INF_F;
            float dhi = (j < NC) ? scs[j] - tk     : CUDART_INF_F;
            float d = fminf(dlo, dhi);
            s += d * d;
            if (j >= 1) atomicMin(&scmin[j - 1], __float_as_uint(dlo));
            if (j < NC) atomicMin(&scmin[j],     __float_as_uint(dhi));
        } else {
            inv = 1;
        }
    }

    #pragma unroll
    for (int o = 16; o; o >>= 1) {
        s    += __shfl_xor_sync(0xFFFFFFFFu, s, o);
        mloc  = fmaxf(mloc, __shfl_xor_sync(0xFFFFFFFFu, mloc, o));
    }
    if (lane == 0) { sred[wid] = s; sred2[wid] = mloc; }
    int banyinv = __syncthreads_or(inv);

    // merge per-block center mins (inverted key; 0 == +inf)
    {
        unsigned sm = scmin[tid];
        if (sm != 0x7F800000u) atomicMax(&g_ckey[b * NC + tid], ~sm);
    }
    if (tid == 0) {
        float bs = sred[0], bm = sred2[0];
        #pragma unroll
        for (int j = 1; j < 8; j++) { bs += sred[j]; bm = fmaxf(bm, sred2[j]); }
        g_d2part[bid] = bs;
        atomicMax(&g_maxkey, fkey(bm));
        if (banyinv) g_anyinv = 1;     // benign same-value race
    }

    // ---------------------------- ticket ----------------------------
    __threadfence();
    if (tid == 0) is_last = (atomicAdd(&g_cnt, 1u) == NBLK - 1);
    __syncthreads();
    if (!is_last) return;
    __threadfence();

    // =========================== FINALIZE (1 block x 256) ===========================
    const float mt = funkey(g_maxkey);
    const float mc = fmaxf(fmaxf(__ldcg(&g_csort[NC - 1]),          __ldcg(&g_csort[NC + NC - 1])),
                           fmaxf(__ldcg(&g_csort[2 * NC + NC - 1]), __ldcg(&g_csort[3 * NC + NC - 1])));
    const float mx = fmaxf(mt, mc), mn = fminf(mt, mc);
    const float pad = mx + (mx - mn) + 1.0f;   // EPS = 1.0
    const int anyinv = g_anyinv;

    // prefetch all 4 batches (MLP), then run the 1-D distance transforms
    float    cB[B];
    unsigned kB[B];
    #pragma unroll
    for (int bb = 0; bb < B; bb++) {
        cB[bb] = __ldcg(&g_csort[bb * NC + tid]);
        kB[bb] = __ldcg(&g_ckey[bb * NC + tid]);
    }
    float acc = 0.0f;
    #pragma unroll
    for (int bb = 0; bb < B; bb++) {
        g_ckey[bb * NC + tid] = 0u;            // reset for next replay
        float c = cB[bb];
        float d = kB[bb] ? __uint_as_float(~kB[bb]) : CUDART_INF_F;
        float As = blk_min_scan(d - c, tid, wa);        // prefix-min of d_j - c_j
        float Bs = blk_min_scan_rev(d + c, tid, wa);    // suffix-min of d_j + c_j
        float Di = fminf(As + c, Bs - c);
        if (anyinv) Di = fminf(Di, pad - c);
        acc += Di * Di;
    }
    if (tid == 0) {
        if (!anyinv) { float dp = pad - mt; acc += dp * dp; }  // pad-center row
        g_cnt = 0u;                            // reset for next replay
        g_flag[0] = 0u; g_flag[1] = 0u; g_flag[2] = 0u; g_flag[3] = 0u;
    }
    for (int i = tid; i < NBLK; i += 256) acc += g_d2part[i];

    #pragma unroll
    for (int o = 16; o; o >>= 1) acc += __shfl_xor_sync(0xFFFFFFFFu, acc, o);
    if ((tid & 31) == 0) sred[wid] = acc;
    __syncthreads();
    if (tid == 0) {
        float tot = sred[0];
        #pragma unroll
        for (int j = 1; j < 8; j++) tot += sred[j];
        out[0] = tot * 0.25f;
    }
}

// ---------------------------------------------------------------------------
extern "C" void kernel_launch(void* const* d_in, const int* in_sizes, int n_in,
                              void* d_out, int out_size) {
    const float4* t4      = (const float4*)d_in[0];
    const float*  centers = (const float*)d_in[1];
    const int4*   m4      = (const int4*)d_in[2];
    float*        out     = (float*)d_out;

    k_fused<<<NBLK, 256>>>(t4, m4, centers, out);
}

// round 17
// speedup vs baseline: 1.0590x; 1.0221x over previous
#include <cuda_runtime.h>
#include <math_constants.h>

#define B       4
#define M       76800          // 240*320 targets per batch
#define NC      256
#define NBLK    300            // 75 chunks x 4 batches; b = bid&3, sub = bid>>2; 1024 targets/block

__device__ unsigned           g_maxkey;        // monotonic masked-max key (idempotent across replays)
__device__ int                g_anyinv;        // any masked-out pixel (idempotent)
__device__ float              g_csort[B * NC]; // sorted centers (published by bids 0..3)
__device__ int                g_start[B * NC]; // bucket-start LUT (published by bids 0..3)
__device__ float              g_meta[B * 2];   // {lo, scale} per batch
__device__ unsigned           g_flag[B];       // release flag (reset by finalizer)
__device__ unsigned           g_ckey[B * NC];  // min dist per sorted slot, INVERTED key; 0 == +inf (reset by finalizer)
__device__ unsigned long long g_d2sum;         // Q32 fixed-point dist2 total (deterministic int adds; reset by finalizer)
__device__ unsigned           g_cnt;            // ticket (reset by finalizer)

__device__ __forceinline__ unsigned fkey(float f) {
    unsigned b = __float_as_uint(f);
    return b ^ ((b & 0x80000000u) ? 0xFFFFFFFFu : 0x80000000u);
}
__device__ __forceinline__ float funkey(unsigned k) {
    return __uint_as_float(k ^ ((k & 0x80000000u) ? 0x80000000u : 0xFFFFFFFFu));
}

__global__ void __launch_bounds__(256) k_fused(const float4* __restrict__ t4,
                                               const int4*   __restrict__ m4,
                                               const float*  __restrict__ centers,
                                               float*        __restrict__ out) {
    __shared__ float    scs[NC];       // sorted centers (identical content on both paths)
    __shared__ float    cval[NC];      // scatter scratch (slow path only)
    __shared__ int      cidx[NC];
    __shared__ int      hist[NC];
    __shared__ int      start[NC + 1];
    __shared__ unsigned scmin[NC];
    __shared__ float    wa[64];        // finalize scan scratch: 16 per batch
    __shared__ int      swa[8];
    __shared__ float    sred[8], sred2[8];
    __shared__ float    smeta[2];
    __shared__ int      sfast;
    __shared__ bool     is_last;

    const int tid  = threadIdx.x;      // 0..255
    const int bid  = blockIdx.x;
    const int lane = tid & 31;
    const int wid  = tid >> 5;         // 0..7
    const int b    = bid & 3;
    const int sub  = bid >> 2;         // 0..74

    // ---- independent flag probe first (hides under target DRAM loads) ----
    unsigned flagv = 0u;
    if (tid == 0 && bid >= B) flagv = __ldcg(&g_flag[b]);

    // ---- kick off DRAM loads (float4/int4: 4 targets/thread) ----
    const int gi = b * (M / 4) + sub * 256 + tid;
    const float4 tv = t4[gi];
    const int4   mv = m4[gi];
    const float tval[4] = {tv.x, tv.y, tv.z, tv.w};
    const int   mok[4]  = {mv.x, mv.y, mv.z, mv.w};

    scmin[tid] = 0x7F800000u;          // +inf
    if (tid == 0) sfast = (flagv != 0u);
    __syncthreads();

    float lo, scale;
    if (sfast) {
        // fast path: 2 coalesced L2 loads, content bitwise-identical to local sort
        __threadfence();               // acquire ordering after flag observe
        scs[tid]   = __ldcg(&g_csort[b * NC + tid]);
        start[tid] = __ldcg(&g_start[b * NC + tid]);
        if (tid == 0) {
            start[NC] = NC;
            smeta[0] = __ldcg(&g_meta[2 * b]);
            smeta[1] = __ldcg(&g_meta[2 * b + 1]);
        }
        __syncthreads();
        lo = smeta[0]; scale = smeta[1];
    } else {
        // slow path: local deterministic counting sort
        const float myc = centers[b * NC + tid];
        hist[tid] = 0;
        __syncthreads();
        {
            float mn = myc, mx = myc;
            #pragma unroll
            for (int o = 16; o; o >>= 1) {
                mn = fminf(mn, __shfl_xor_sync(0xFFFFFFFFu, mn, o));
                mx = fmaxf(mx, __shfl_xor_sync(0xFFFFFFFFu, mx, o));
            }
            if (lane == 0) { wa[wid] = mn; wa[8 + wid] = mx; }
        }
        __syncthreads();
        lo = wa[0]; float hi = wa[8];
        #pragma unroll
        for (int j = 1; j < 8; j++) { lo = fminf(lo, wa[j]); hi = fmaxf(hi, wa[8 + j]); }
        scale = (hi > lo) ? 256.0f / (hi - lo) : 0.0f;

        const int myq = min(255, max(0, (int)((myc - lo) * scale)));
        const int myrank = atomicAdd(&hist[myq], 1);
        __syncthreads();
        {
            int h = hist[tid], incl = h;
            #pragma unroll
            for (int o = 1; o < 32; o <<= 1) {
                int u = __shfl_up_sync(0xFFFFFFFFu, incl, o);
                if (lane >= o) incl += u;
            }
            if (lane == 31) swa[wid] = incl;
            __syncthreads();
            int add = 0;
            #pragma unroll
            for (int j = 0; j < 8; j++)
                if (j < wid) add += swa[j];
            start[tid] = add + incl - h;
            if (tid == 0) start[NC] = NC;
        }
        __syncthreads();
        {
            int p = start[myq] + myrank;
            cval[p] = myc; cidx[p] = tid;
        }
        __syncthreads();
        {
            const int s0 = start[myq], e0 = start[myq + 1];
            int rb = 0;
            for (int j = s0; j < e0; j++) {
                float cv = cval[j];
                if (cv < myc || (cv == myc && cidx[j] < tid)) rb++;
            }
            scs[s0 + rb] = myc;        // fully sorted, deterministic order
        }
        __syncthreads();

        if (bid < B) {                 // publish for fast-path blocks + finalizer
            g_csort[b * NC + tid] = scs[tid];
            g_start[b * NC + tid] = start[tid];
            if (tid == 0) { g_meta[2 * b] = lo; g_meta[2 * b + 1] = scale; }
            __threadfence();
            __syncthreads();
            if (tid == 0) atomicExch(&g_flag[b], 1u);
        }
    }

    // ---- main pass: 4 targets, bucket-LUT bracket (independent chains -> ILP) ----
    float s = 0.0f;
    float mloc = -CUDART_INF_F;
    int inv = 0;
    #pragma unroll
    for (int q = 0; q < 4; q++) {
        const float tk = tval[q];
        if (mok[q]) {
            mloc = fmaxf(mloc, tk);
            int qt = min(255, max(0, (int)((tk - lo) * scale)));
            int j = start[qt], e = start[qt + 1];
            while (j < e && scs[j] <= tk) j++;     // exact lower-bound count
            float dlo = (j >= 1) ? tk - scs[j - 1] : CUDART_INF_F;
            float dhi = (j < NC) ? scs[j] - tk     : CUDART_INF_F;
            float d = fminf(dlo, dhi);
            s += d * d;
            if (j >= 1) atomicMin(&scmin[j - 1], __float_as_uint(dlo));
            if (j < NC) atomicMin(&scmin[j],     __float_as_uint(dhi));
        } else {
            inv = 1;
        }
    }

    #pragma unroll
    for (int o = 16; o; o >>= 1) {
        s    += __shfl_xor_sync(0xFFFFFFFFu, s, o);
        mloc  = fmaxf(mloc, __shfl_xor_sync(0xFFFFFFFFu, mloc, o));
    }
    if (lane == 0) { sred[wid] = s; sred2[wid] = mloc; }
    int banyinv = __syncthreads_or(inv);

    // merge per-block center mins (inverted key; 0 == +inf)
    {
        unsigned sm = scmin[tid];
        if (sm != 0x7F800000u) atomicMax(&g_ckey[b * NC + tid], ~sm);
    }
    if (tid == 0) {
        float bs = sred[0], bm = sred2[0];
        #pragma unroll
        for (int j = 1; j < 8; j++) { bs += sred[j]; bm = fmaxf(bm, sred2[j]); }
        // deterministic Q32 fixed-point accumulation (integer adds are associative)
        atomicAdd(&g_d2sum, (unsigned long long)((double)bs * 4294967296.0 + 0.5));
        atomicMax(&g_maxkey, fkey(bm));
        if (banyinv) g_anyinv = 1;     // benign same-value race
    }

    // ---------------------------- ticket ----------------------------
    __threadfence();
    if (tid == 0) is_last = (atomicAdd(&g_cnt, 1u) == NBLK - 1);
    __syncthreads();
    if (!is_last) return;
    __threadfence();

    // =========================== FINALIZE (1 block x 256) ===========================
    const float mt = funkey(g_maxkey);
    const float mc = fmaxf(fmaxf(__ldcg(&g_csort[NC - 1]),          __ldcg(&g_csort[NC + NC - 1])),
                           fmaxf(__ldcg(&g_csort[2 * NC + NC - 1]), __ldcg(&g_csort[3 * NC + NC - 1])));
    const float mx = fmaxf(mt, mc), mn = fminf(mt, mc);
    const float pad = mx + (mx - mn) + 1.0f;   // EPS = 1.0
    const int anyinv = g_anyinv;

    // prefetch all 4 batches (MLP), then run the 1-D distance transforms
    float    cB[B];
    unsigned kB[B];
    #pragma unroll
    for (int bb = 0; bb < B; bb++) {
        cB[bb] = __ldcg(&g_csort[bb * NC + tid]);
        kB[bb] = __ldcg(&g_ckey[bb * NC + tid]);
    }
    float acc = 0.0f;
    #pragma unroll
    for (int bb = 0; bb < B; bb++) {
        g_ckey[bb * NC + tid] = 0u;            // reset for next replay
        const float c = cB[bb];
        const float d = kB[bb] ? __uint_as_float(~kB[bb]) : CUDART_INF_F;

        // fused prefix-min(d-c) and suffix-min(d+c): ONE barrier per batch
        float v1 = d - c, v2 = d + c;
        #pragma unroll
        for (int o = 1; o < 32; o <<= 1) {
            float u1 = __shfl_up_sync(0xFFFFFFFFu, v1, o);
            float u2 = __shfl_down_sync(0xFFFFFFFFu, v2, o);
            if (lane >= o)      v1 = fminf(v1, u1);
            if (lane + o < 32)  v2 = fminf(v2, u2);
        }
        if (lane == 31) wa[bb * 16 + wid]     = v1;
        if (lane == 0)  wa[bb * 16 + 8 + wid] = v2;
        __syncthreads();
        float pre = CUDART_INF_F, suf = CUDART_INF_F;
        #pragma unroll
        for (int j = 0; j < 7; j++)
            if (j < wid) pre = fminf(pre, wa[bb * 16 + j]);
        #pragma unroll
        for (int j = 1; j < 8; j++)
            if (j > wid) suf = fminf(suf, wa[bb * 16 + 8 + j]);
        float As = fminf(v1, pre);
        float Bs = fminf(v2, suf);

        float Di = fminf(As + c, Bs - c);
        if (anyinv) Di = fminf(Di, pad - c);
        acc += Di * Di;
    }
    if (tid == 0) {
        acc += (float)((double)g_d2sum * (1.0 / 4294967296.0));   // dist2 total
        if (!anyinv) { float dp = pad - mt; acc += dp * dp; }     // pad-center row
        g_d2sum = 0ull;                       // resets for next replay
        g_cnt = 0u;
        g_flag[0] = 0u; g_flag[1] = 0u; g_flag[2] = 0u; g_flag[3] = 0u;
    }

    #pragma unroll
    for (int o = 16; o; o >>= 1) acc += __shfl_xor_sync(0xFFFFFFFFu, acc, o);
    if (lane == 0) sred[wid] = acc;
    __syncthreads();
    if (tid == 0) {
        float tot = sred[0];
        #pragma unroll
        for (int j = 1; j < 8; j++) tot += sred[j];
        out[0] = tot * 0.25f;
    }
}

// ---------------------------------------------------------------------------
extern "C" void kernel_launch(void* const* d_in, const int* in_sizes, int n_in,
                              void* d_out, int out_size) {
    const float4* t4      = (const float4*)d_in[0];
    const float*  centers = (const float*)d_in[1];
    const int4*   m4      = (const int4*)d_in[2];
    float*        out     = (float*)d_out;

    k_fused<<<NBLK, 256>>>(t4, m4, centers, out);
}